// round 11
// baseline (speedup 1.0000x reference)
#include <cuda_runtime.h>

#define BB 8
#define LL 2048
#define HH 8
#define EE 64
#define MM 64
#define LHALF 1024
#define NCHUNK 4

typedef unsigned long long ull;

// Scratch (device globals — no allocation allowed). 16B-aligned for vector ops.
// Single duplicated-cosine twiddle table: g_twd[k] = (cos(2πk/2048), cos(...)).
// -sin(2πk/2048) = cos(2π(k+512)/2048), so one table serves both factors.
__device__ __align__(16) ull g_twd[LL];
__device__ __align__(16) ull g_Xpr[NCHUNK][BB*HH*MM*EE/2];     // fwd partial Re: [c][bh][m][i/2]
__device__ __align__(16) ull g_Xpi[NCHUNK][BB*HH*MM*EE/2];     // fwd partial Im
__device__ __align__(16) float g_Yr[BB*HH*MM*EE];              // modes Re: [bh][m][o]
__device__ __align__(16) float g_Yi[BB*HH*MM*EE];              // modes Im
__device__ __align__(16) float g_Wtr[HH*MM*EE*EE];             // w_real: [h][m][i][o]
__device__ __align__(16) float g_Wti[HH*MM*EE*EE];             // w_imag: [h][m][i][o]

__device__ __forceinline__ ull fma2(ull a, ull b, ull c) {
    ull d;
    asm("fma.rn.f32x2 %0, %1, %2, %3;" : "=l"(d) : "l"(a), "l"(b), "l"(c));
    return d;
}
__device__ __forceinline__ ull add2(ull a, ull b) {
    ull d;
    asm("add.rn.f32x2 %0, %1, %2;" : "=l"(d) : "l"(a), "l"(b));
    return d;
}
__device__ __forceinline__ ull pack2(float x, float y) {
    ull r; asm("mov.b64 %0, {%1, %2};" : "=l"(r) : "f"(x), "f"(y)); return r;
}
__device__ __forceinline__ float2 unpack2(ull v) {
    float2 r; asm("mov.b64 {%0, %1}, %2;" : "=f"(r.x), "=f"(r.y) : "l"(v)); return r;
}

// ---------------------------------------------------------------------------
// Setup: W transpose [h][i][o][m] -> [h][m][i][o], plus (block 0) the
// duplicated-cosine twiddle table.
// ---------------------------------------------------------------------------
__global__ void __launch_bounds__(256) k_trans(const float* __restrict__ wre,
                                               const float* __restrict__ wim) {
    __shared__ float t[EE][EE + 1];
    const int h = blockIdx.x >> 6;
    const int i = blockIdx.x & 63;
    const int tid = threadIdx.x;
    const size_t in_base = (size_t)blockIdx.x * (EE * MM);
    const size_t out_base = (size_t)h * (MM * EE * EE) + (size_t)i * EE;

    if (blockIdx.x == 0) {
        for (int k = tid; k < LL; k += 256) {
            float cw = cospif((float)k * (1.0f / 1024.0f));
            g_twd[k] = pack2(cw, cw);
        }
    }

    for (int idx = tid; idx < EE * MM; idx += 256) t[idx >> 6][idx & 63] = wre[in_base + idx];
    __syncthreads();
    for (int idx = tid; idx < MM * EE; idx += 256) {
        const int m = idx >> 6, o = idx & 63;
        g_Wtr[out_base + (size_t)m * (EE * EE) + o] = t[o][m];
    }
    __syncthreads();
    for (int idx = tid; idx < EE * MM; idx += 256) t[idx >> 6][idx & 63] = wim[in_base + idx];
    __syncthreads();
    for (int idx = tid; idx < MM * EE; idx += 256) {
        const int m = idx >> 6, o = idx & 63;
        g_Wti[out_base + (size_t)m * (EE * EE) + o] = t[o][m];
    }
}

// ---------------------------------------------------------------------------
// Forward truncated DFT, radix-2 fold, i-vectorized (round-7 shape: 4B/fma2).
// Grid (bh=64, lchunk=4). Block 128. Thread tile: 4 m x 8 i. 8 stages of 32 l.
// ---------------------------------------------------------------------------
__global__ void __launch_bounds__(128) k_fwd(const float* __restrict__ x) {
    __shared__ __align__(16) ull   s_twd[LL];      // 16 KB (dup-cos)
    __shared__ __align__(16) float s_u[32][EE];    // 8 KB
    __shared__ __align__(16) float s_v[32][EE];    // 8 KB
    const int tid = threadIdx.x;
    const int bh = blockIdx.x;
    const int b = bh >> 3, h = bh & 7;
    const int c = blockIdx.y;

    for (int i = tid; i < LL; i += 128) s_twd[i] = g_twd[i];

    const int i0 = (tid & 7) * 8;
    const int m0 = (tid >> 3) * 4;   // 0..60, multiple of 4 -> parity(m0+j)=j&1

    ull aR[4][4], aI[4][4];
    #pragma unroll
    for (int j = 0; j < 4; ++j)
        #pragma unroll
        for (int k = 0; k < 4; ++k) { aR[j][k] = 0ull; aI[j][k] = 0ull; }

    const float* xb = x + ((size_t)b * LL * HH + h) * EE;

    for (int stage = 0; stage < 8; ++stage) {
        const int lbase = c * 256 + stage * 32;
        __syncthreads();
        for (int idx4 = tid; idx4 < 32 * 16; idx4 += 128) {
            const int sl = idx4 >> 4;
            const int ii = (idx4 & 15) * 4;
            const float4 a = *(const float4*)&xb[(size_t)(lbase + sl) * (HH * EE) + ii];
            const float4 d = *(const float4*)&xb[(size_t)(lbase + sl + LHALF) * (HH * EE) + ii];
            *(float4*)&s_u[sl][ii] = make_float4(a.x + d.x, a.y + d.y, a.z + d.z, a.w + d.w);
            *(float4*)&s_v[sl][ii] = make_float4(a.x - d.x, a.y - d.y, a.z - d.z, a.w - d.w);
        }
        __syncthreads();
        #pragma unroll 2
        for (int sl = 0; sl < 32; ++sl) {
            const int l = lbase + sl;
            const ulonglong2 U0 = *(const ulonglong2*)&s_u[sl][i0];
            const ulonglong2 U1 = *(const ulonglong2*)&s_u[sl][i0 + 4];
            const ulonglong2 V0 = *(const ulonglong2*)&s_v[sl][i0];
            const ulonglong2 V1 = *(const ulonglong2*)&s_v[sl][i0 + 4];
            #pragma unroll
            for (int j = 0; j < 4; ++j) {
                const int idx = ((m0 + j) * l) & (LL - 1);
                const ull cc = s_twd[idx];
                const ull ss = s_twd[(idx + 512) & (LL - 1)];   // (-sin,-sin)
                if (j & 1) {
                    aR[j][0] = fma2(V0.x, cc, aR[j][0]); aI[j][0] = fma2(V0.x, ss, aI[j][0]);
                    aR[j][1] = fma2(V0.y, cc, aR[j][1]); aI[j][1] = fma2(V0.y, ss, aI[j][1]);
                    aR[j][2] = fma2(V1.x, cc, aR[j][2]); aI[j][2] = fma2(V1.x, ss, aI[j][2]);
                    aR[j][3] = fma2(V1.y, cc, aR[j][3]); aI[j][3] = fma2(V1.y, ss, aI[j][3]);
                } else {
                    aR[j][0] = fma2(U0.x, cc, aR[j][0]); aI[j][0] = fma2(U0.x, ss, aI[j][0]);
                    aR[j][1] = fma2(U0.y, cc, aR[j][1]); aI[j][1] = fma2(U0.y, ss, aI[j][1]);
                    aR[j][2] = fma2(U1.x, cc, aR[j][2]); aI[j][2] = fma2(U1.x, ss, aI[j][2]);
                    aR[j][3] = fma2(U1.y, cc, aR[j][3]); aI[j][3] = fma2(U1.y, ss, aI[j][3]);
                }
            }
        }
    }

    #pragma unroll
    for (int j = 0; j < 4; ++j) {
        const size_t base = ((size_t)bh * MM + (m0 + j)) * (EE / 2) + (i0 >> 1);
        ull* pr = &g_Xpr[c][base];
        ull* pi = &g_Xpi[c][base];
        pr[0] = aR[j][0]; pr[1] = aR[j][1]; pr[2] = aR[j][2]; pr[3] = aR[j][3];
        pi[0] = aI[j][0]; pi[1] = aI[j][1]; pi[2] = aI[j][2]; pi[3] = aI[j][3];
    }
}

// ---------------------------------------------------------------------------
// Mode mixing per (m,h): reduce NCHUNK partials, complex GEMM over i, fold
// irfft scale (m==0?1:2)/L. Writes separated Re/Im for k_inv.
// ---------------------------------------------------------------------------
__global__ void __launch_bounds__(128) k_mix() {
    __shared__ __align__(16) float sXr[BB][EE], sXi[BB][EE];
    __shared__ __align__(16) float sWr[EE][EE], sWi[EE][EE];
    const int m = blockIdx.x, h = blockIdx.y;
    const int tid = threadIdx.x;

    for (int idx = tid; idx < BB * EE / 2; idx += 128) {
        const int b = idx >> 5, ip = idx & 31;
        float xr0 = 0.f, xr1 = 0.f, xi0 = 0.f, xi1 = 0.f;
        const size_t offp = (((size_t)(b * HH + h)) * MM + m) * (EE / 2) + ip;
        #pragma unroll
        for (int cc = 0; cc < NCHUNK; ++cc) {
            const float2 r = unpack2(g_Xpr[cc][offp]);
            const float2 i2 = unpack2(g_Xpi[cc][offp]);
            xr0 += r.x; xr1 += r.y; xi0 += i2.x; xi1 += i2.y;
        }
        sXr[b][2 * ip] = xr0; sXr[b][2 * ip + 1] = xr1;
        sXi[b][2 * ip] = xi0; sXi[b][2 * ip + 1] = xi1;
    }
    const size_t wbase = ((size_t)h * MM + m) * (EE * EE);
    for (int idx = tid; idx < EE * EE; idx += 128) {
        sWr[idx >> 6][idx & 63] = g_Wtr[wbase + idx];
        sWi[idx >> 6][idx & 63] = g_Wti[wbase + idx];
    }
    __syncthreads();

    const int b = tid >> 4;
    const int o0 = (tid & 15) * 4;
    float ar0 = 0, ar1 = 0, ar2 = 0, ar3 = 0;
    float ai0 = 0, ai1 = 0, ai2 = 0, ai3 = 0;
    #pragma unroll 4
    for (int i = 0; i < EE; ++i) {
        const float xr = sXr[b][i], xi = sXi[b][i];
        const float4 w_r = *(const float4*)&sWr[i][o0];
        const float4 w_i = *(const float4*)&sWi[i][o0];
        ar0 = fmaf(xr, w_r.x, ar0); ar0 = fmaf(-xi, w_i.x, ar0);
        ai0 = fmaf(xr, w_i.x, ai0); ai0 = fmaf( xi, w_r.x, ai0);
        ar1 = fmaf(xr, w_r.y, ar1); ar1 = fmaf(-xi, w_i.y, ar1);
        ai1 = fmaf(xr, w_i.y, ai1); ai1 = fmaf( xi, w_r.y, ai1);
        ar2 = fmaf(xr, w_r.z, ar2); ar2 = fmaf(-xi, w_i.z, ar2);
        ai2 = fmaf(xr, w_i.z, ai2); ai2 = fmaf( xi, w_r.z, ai2);
        ar3 = fmaf(xr, w_r.w, ar3); ar3 = fmaf(-xi, w_i.w, ar3);
        ai3 = fmaf(xr, w_i.w, ai3); ai3 = fmaf( xi, w_r.w, ai3);
    }
    const float sc = (m == 0 ? 1.0f : 2.0f) * (1.0f / (float)LL);
    const size_t dst = (((size_t)(b * HH + h)) * MM + m) * EE + o0;
    *(float4*)&g_Yr[dst] = make_float4(ar0 * sc, ar1 * sc, ar2 * sc, ar3 * sc);
    *(float4*)&g_Yi[dst] = make_float4(ai0 * sc, ai1 * sc, ai2 * sc, ai3 * sc);
}

// ---------------------------------------------------------------------------
// Inverse truncated DFT, radix-2 fold, o-vectorized, 4-l register tile:
// per m, data loads (R/I, 4 LDS.128) amortize over 4 l and twiddle loads
// (8 LDS.64) amortize over 8 o -> 128B per 32 fma2 = 4 B/fma2.
// Grid (bh=64, lchunk=8, ohalf=2). Block 128. Thread: 4 folded l x 8 o.
// ---------------------------------------------------------------------------
__global__ void __launch_bounds__(128) k_inv(float* __restrict__ y) {
    __shared__ __align__(16) ull   s_twd[LL];       // 16 KB (dup-cos)
    __shared__ __align__(16) float s_Yr[MM * 32];   // 8 KB  [m][o-half]
    __shared__ __align__(16) float s_Yi[MM * 32];   // 8 KB
    const int tid = threadIdx.x;
    const int bh = blockIdx.x;
    const int b = bh >> 3, h = bh & 7;
    const int lc = blockIdx.y;
    const int oh = blockIdx.z;

    for (int i = tid; i < LL; i += 128) s_twd[i] = g_twd[i];
    {
        const size_t src = (size_t)bh * (MM * EE) + oh * 32;
        for (int idx = tid; idx < MM * 32; idx += 128) {
            const int m = idx >> 5, o = idx & 31;
            s_Yr[idx] = g_Yr[src + (size_t)m * EE + o];
            s_Yi[idx] = g_Yi[src + (size_t)m * EE + o];
        }
    }
    __syncthreads();

    const int o0 = (tid & 3) * 8;              // local o in half
    const int lg = tid >> 2;                   // 0..31
    const int l0 = lc * 128 + lg * 4;          // 4 consecutive l
    const int o_g = oh * 32 + o0;              // global o
    float* yb = y + ((size_t)b * LL * HH + h) * EE + o_g;
    const ull m1 = pack2(-1.0f, -1.0f);

    // accumulators: [l-slot][o-ull], even-m (E) and odd-m (O)
    ull ae[4][4], ao[4][4];
    #pragma unroll
    for (int t = 0; t < 4; ++t)
        #pragma unroll
        for (int k = 0; k < 4; ++k) { ae[t][k] = 0; ao[t][k] = 0; }

    // twiddle index trackers: i_t = (m * (l0+t)) & 2047
    int i0 = 0, i1 = 0, i2 = 0, i3 = 0;
    const int d0 = l0, d1 = l0 + 1, d2 = l0 + 2, d3 = l0 + 3;

    #pragma unroll 2
    for (int m = 0; m < MM; m += 2) {
        {   // even m -> ae
            const ulonglong2 R0 = *(const ulonglong2*)&s_Yr[m * 32 + o0];
            const ulonglong2 R1 = *(const ulonglong2*)&s_Yr[m * 32 + o0 + 4];
            const ulonglong2 I0 = *(const ulonglong2*)&s_Yi[m * 32 + o0];
            const ulonglong2 I1 = *(const ulonglong2*)&s_Yi[m * 32 + o0 + 4];
            const ull c0 = s_twd[i0], s0 = s_twd[(i0 + 512) & (LL - 1)];
            const ull c1 = s_twd[i1], s1 = s_twd[(i1 + 512) & (LL - 1)];
            const ull c2 = s_twd[i2], s2 = s_twd[(i2 + 512) & (LL - 1)];
            const ull c3 = s_twd[i3], s3 = s_twd[(i3 + 512) & (LL - 1)];
            ae[0][0] = fma2(R0.x, c0, ae[0][0]); ae[0][0] = fma2(I0.x, s0, ae[0][0]);
            ae[0][1] = fma2(R0.y, c0, ae[0][1]); ae[0][1] = fma2(I0.y, s0, ae[0][1]);
            ae[0][2] = fma2(R1.x, c0, ae[0][2]); ae[0][2] = fma2(I1.x, s0, ae[0][2]);
            ae[0][3] = fma2(R1.y, c0, ae[0][3]); ae[0][3] = fma2(I1.y, s0, ae[0][3]);
            ae[1][0] = fma2(R0.x, c1, ae[1][0]); ae[1][0] = fma2(I0.x, s1, ae[1][0]);
            ae[1][1] = fma2(R0.y, c1, ae[1][1]); ae[1][1] = fma2(I0.y, s1, ae[1][1]);
            ae[1][2] = fma2(R1.x, c1, ae[1][2]); ae[1][2] = fma2(I1.x, s1, ae[1][2]);
            ae[1][3] = fma2(R1.y, c1, ae[1][3]); ae[1][3] = fma2(I1.y, s1, ae[1][3]);
            ae[2][0] = fma2(R0.x, c2, ae[2][0]); ae[2][0] = fma2(I0.x, s2, ae[2][0]);
            ae[2][1] = fma2(R0.y, c2, ae[2][1]); ae[2][1] = fma2(I0.y, s2, ae[2][1]);
            ae[2][2] = fma2(R1.x, c2, ae[2][2]); ae[2][2] = fma2(I1.x, s2, ae[2][2]);
            ae[2][3] = fma2(R1.y, c2, ae[2][3]); ae[2][3] = fma2(I1.y, s2, ae[2][3]);
            ae[3][0] = fma2(R0.x, c3, ae[3][0]); ae[3][0] = fma2(I0.x, s3, ae[3][0]);
            ae[3][1] = fma2(R0.y, c3, ae[3][1]); ae[3][1] = fma2(I0.y, s3, ae[3][1]);
            ae[3][2] = fma2(R1.x, c3, ae[3][2]); ae[3][2] = fma2(I1.x, s3, ae[3][2]);
            ae[3][3] = fma2(R1.y, c3, ae[3][3]); ae[3][3] = fma2(I1.y, s3, ae[3][3]);
            i0 = (i0 + d0) & (LL - 1); i1 = (i1 + d1) & (LL - 1);
            i2 = (i2 + d2) & (LL - 1); i3 = (i3 + d3) & (LL - 1);
        }
        {   // odd m+1 -> ao
            const ulonglong2 R0 = *(const ulonglong2*)&s_Yr[(m + 1) * 32 + o0];
            const ulonglong2 R1 = *(const ulonglong2*)&s_Yr[(m + 1) * 32 + o0 + 4];
            const ulonglong2 I0 = *(const ulonglong2*)&s_Yi[(m + 1) * 32 + o0];
            const ulonglong2 I1 = *(const ulonglong2*)&s_Yi[(m + 1) * 32 + o0 + 4];
            const ull c0 = s_twd[i0], s0 = s_twd[(i0 + 512) & (LL - 1)];
            const ull c1 = s_twd[i1], s1 = s_twd[(i1 + 512) & (LL - 1)];
            const ull c2 = s_twd[i2], s2 = s_twd[(i2 + 512) & (LL - 1)];
            const ull c3 = s_twd[i3], s3 = s_twd[(i3 + 512) & (LL - 1)];
            ao[0][0] = fma2(R0.x, c0, ao[0][0]); ao[0][0] = fma2(I0.x, s0, ao[0][0]);
            ao[0][1] = fma2(R0.y, c0, ao[0][1]); ao[0][1] = fma2(I0.y, s0, ao[0][1]);
            ao[0][2] = fma2(R1.x, c0, ao[0][2]); ao[0][2] = fma2(I1.x, s0, ao[0][2]);
            ao[0][3] = fma2(R1.y, c0, ao[0][3]); ao[0][3] = fma2(I1.y, s0, ao[0][3]);
            ao[1][0] = fma2(R0.x, c1, ao[1][0]); ao[1][0] = fma2(I0.x, s1, ao[1][0]);
            ao[1][1] = fma2(R0.y, c1, ao[1][1]); ao[1][1] = fma2(I0.y, s1, ao[1][1]);
            ao[1][2] = fma2(R1.x, c1, ao[1][2]); ao[1][2] = fma2(I1.x, s1, ao[1][2]);
            ao[1][3] = fma2(R1.y, c1, ao[1][3]); ao[1][3] = fma2(I1.y, s1, ao[1][3]);
            ao[2][0] = fma2(R0.x, c2, ao[2][0]); ao[2][0] = fma2(I0.x, s2, ao[2][0]);
            ao[2][1] = fma2(R0.y, c2, ao[2][1]); ao[2][1] = fma2(I0.y, s2, ao[2][1]);
            ao[2][2] = fma2(R1.x, c2, ao[2][2]); ao[2][2] = fma2(I1.x, s2, ao[2][2]);
            ao[2][3] = fma2(R1.y, c2, ao[2][3]); ao[2][3] = fma2(I1.y, s2, ao[2][3]);
            ao[3][0] = fma2(R0.x, c3, ao[3][0]); ao[3][0] = fma2(I0.x, s3, ao[3][0]);
            ao[3][1] = fma2(R0.y, c3, ao[3][1]); ao[3][1] = fma2(I0.y, s3, ao[3][1]);
            ao[3][2] = fma2(R1.x, c3, ao[3][2]); ao[3][2] = fma2(I1.x, s3, ao[3][2]);
            ao[3][3] = fma2(R1.y, c3, ao[3][3]); ao[3][3] = fma2(I1.y, s3, ao[3][3]);
            i0 = (i0 + d0) & (LL - 1); i1 = (i1 + d1) & (LL - 1);
            i2 = (i2 + d2) & (LL - 1); i3 = (i3 + d3) & (LL - 1);
        }
    }

    // y_l = E+O ; y_{l+1024} = E-O
    #pragma unroll
    for (int t = 0; t < 4; ++t) {
        const int l = l0 + t;
        ulonglong2 lo0, lo1, hi0, hi1;
        lo0.x = add2(ae[t][0], ao[t][0]); lo0.y = add2(ae[t][1], ao[t][1]);
        lo1.x = add2(ae[t][2], ao[t][2]); lo1.y = add2(ae[t][3], ao[t][3]);
        hi0.x = fma2(ao[t][0], m1, ae[t][0]); hi0.y = fma2(ao[t][1], m1, ae[t][1]);
        hi1.x = fma2(ao[t][2], m1, ae[t][2]); hi1.y = fma2(ao[t][3], m1, ae[t][3]);
        *(ulonglong2*)&yb[(size_t)l * (HH * EE)]               = lo0;
        *(ulonglong2*)&yb[(size_t)l * (HH * EE) + 4]           = lo1;
        *(ulonglong2*)&yb[(size_t)(l + LHALF) * (HH * EE)]     = hi0;
        *(ulonglong2*)&yb[(size_t)(l + LHALF) * (HH * EE) + 4] = hi1;
    }
}

extern "C" void kernel_launch(void* const* d_in, const int* in_sizes, int n_in,
                              void* d_out, int out_size) {
    (void)in_sizes; (void)n_in; (void)out_size;
    const float* x   = (const float*)d_in[0];
    const float* wre = (const float*)d_in[1];
    const float* wim = (const float*)d_in[2];
    float* y = (float*)d_out;

    k_trans<<<512, 256>>>(wre, wim);
    k_fwd<<<dim3(64, NCHUNK), 128>>>(x);
    k_mix<<<dim3(MM, HH), 128>>>();
    k_inv<<<dim3(64, 8, 2), 128>>>(y);
}

// round 14
// speedup vs baseline: 1.2144x; 1.2144x over previous
#include <cuda_runtime.h>
#include <cuda_bf16.h>
#include <cstdint>

#define BB 8
#define LL 2048
#define HH 8
#define EE 64
#define MM 64
#define LHALF 1024
#define NCHUNK 4

typedef unsigned long long ull;

// ---------------------------------------------------------------------------
// Device scratch (no allocation allowed)
// ---------------------------------------------------------------------------
__device__ __align__(16) ull g_twd[LL];                        // (cos,cos) dup table (fwd)
__device__ __align__(16) ull g_Xpr[NCHUNK][BB*HH*MM*EE/2];     // fwd partial Re
__device__ __align__(16) ull g_Xpi[NCHUNK][BB*HH*MM*EE/2];     // fwd partial Im
__device__ __align__(16) float g_Wtr[HH*MM*EE*EE];             // w_real: [h][m][i][o]
__device__ __align__(16) float g_Wti[HH*MM*EE*EE];             // w_imag: [h][m][i][o]
// Inverse-DFT tensor operands:
// A[par][l][k] (k=2j+ri): cos / -sin of m=2j+par at angle m*l, bf16 hi/lo
__device__ __align__(16) __nv_bfloat16 g_Ah[2][1024*64];
__device__ __align__(16) __nv_bfloat16 g_Al[2][1024*64];
// B: Y modes, [bh][par][o][k=2j+ri] K-major, bf16 hi/lo
__device__ __align__(16) __nv_bfloat16 g_Ybh[BB*HH*2*64*64];
__device__ __align__(16) __nv_bfloat16 g_Ybl[BB*HH*2*64*64];

__device__ __forceinline__ ull fma2(ull a, ull b, ull c) {
    ull d;
    asm("fma.rn.f32x2 %0, %1, %2, %3;" : "=l"(d) : "l"(a), "l"(b), "l"(c));
    return d;
}
__device__ __forceinline__ ull pack2(float x, float y) {
    ull r; asm("mov.b64 %0, {%1, %2};" : "=l"(r) : "f"(x), "f"(y)); return r;
}
__device__ __forceinline__ float2 unpack2(ull v) {
    float2 r; asm("mov.b64 {%0, %1}, %2;" : "=f"(r.x), "=f"(r.y) : "l"(v)); return r;
}
__device__ __forceinline__ uint32_t smem_to_u32(const void* p) {
    uint32_t a;
    asm("{ .reg .u64 t; cvta.to.shared.u64 t, %1; cvt.u32.u64 %0, t; }" : "=r"(a) : "l"(p));
    return a;
}
__device__ __forceinline__ void ldsm_x4(uint32_t& r0, uint32_t& r1, uint32_t& r2, uint32_t& r3,
                                        uint32_t a) {
    asm volatile("ldmatrix.sync.aligned.m8n8.x4.shared.b16 {%0,%1,%2,%3}, [%4];"
                 : "=r"(r0), "=r"(r1), "=r"(r2), "=r"(r3) : "r"(a));
}
__device__ __forceinline__ void ldsm_x2(uint32_t& r0, uint32_t& r1, uint32_t a) {
    asm volatile("ldmatrix.sync.aligned.m8n8.x2.shared.b16 {%0,%1}, [%2];"
                 : "=r"(r0), "=r"(r1) : "r"(a));
}
__device__ __forceinline__ void mma_bf16(float* c, uint32_t a0, uint32_t a1, uint32_t a2,
                                         uint32_t a3, uint32_t b0, uint32_t b1) {
    asm volatile("mma.sync.aligned.m16n8k16.row.col.f32.bf16.bf16.f32 "
                 "{%0,%1,%2,%3}, {%4,%5,%6,%7}, {%8,%9}, {%0,%1,%2,%3};"
                 : "+f"(c[0]), "+f"(c[1]), "+f"(c[2]), "+f"(c[3])
                 : "r"(a0), "r"(a1), "r"(a2), "r"(a3), "r"(b0), "r"(b1));
}

// Inverse kernel smem layout (144-byte padded rows -> ldmatrix conflict-free)
#define ROWB 144
#define OFF_AEH 0
#define OFF_AEL (OFF_AEH + 128 * ROWB)
#define OFF_AOH (OFF_AEL + 128 * ROWB)
#define OFF_AOL (OFF_AOH + 128 * ROWB)
#define OFF_BEH (OFF_AOL + 128 * ROWB)
#define OFF_BEL (OFF_BEH + 64 * ROWB)
#define OFF_BOH (OFF_BEL + 64 * ROWB)
#define OFF_BOL (OFF_BOH + 64 * ROWB)
#define SMEM_INV (OFF_BOL + 64 * ROWB)     // 110,592 B

// ---------------------------------------------------------------------------
// Setup: W transpose + twiddle table + inverse A matrices (bf16 hi/lo)
// ---------------------------------------------------------------------------
__global__ void __launch_bounds__(256) k_trans(const float* __restrict__ wre,
                                               const float* __restrict__ wim) {
    const int tid = threadIdx.x;

    if (blockIdx.x >= 512) {
        // A-matrix generation: blocks 512..575, 16 l-rows each
        const int l0 = (blockIdx.x - 512) * 16;
        for (int idx = tid; idx < 16 * 128; idx += 256) {
            const int l = l0 + (idx >> 7);
            const int rem = idx & 127;
            const int par = rem >> 6;
            const int kk = rem & 63;
            const int m = ((kk >> 1) << 1) + par;
            const int ri = kk & 1;
            const int ang = (m * l) & (LL - 1);
            float s, c;
            sincospif((float)ang * (1.0f / 1024.0f), &s, &c);
            const float v = ri ? -s : c;
            const __nv_bfloat16 hi = __float2bfloat16(v);
            g_Ah[par][l * 64 + kk] = hi;
            g_Al[par][l * 64 + kk] = __float2bfloat16(v - __bfloat162float(hi));
        }
        return;
    }

    __shared__ float t[EE][EE + 1];
    const int h = blockIdx.x >> 6;
    const int i = blockIdx.x & 63;
    const size_t in_base = (size_t)blockIdx.x * (EE * MM);
    const size_t out_base = (size_t)h * (MM * EE * EE) + (size_t)i * EE;

    if (blockIdx.x == 0) {
        for (int k = tid; k < LL; k += 256) {
            float cw = cospif((float)k * (1.0f / 1024.0f));
            g_twd[k] = pack2(cw, cw);
        }
    }

    for (int idx = tid; idx < EE * MM; idx += 256) t[idx >> 6][idx & 63] = wre[in_base + idx];
    __syncthreads();
    for (int idx = tid; idx < MM * EE; idx += 256) {
        const int m = idx >> 6, o = idx & 63;
        g_Wtr[out_base + (size_t)m * (EE * EE) + o] = t[o][m];
    }
    __syncthreads();
    for (int idx = tid; idx < EE * MM; idx += 256) t[idx >> 6][idx & 63] = wim[in_base + idx];
    __syncthreads();
    for (int idx = tid; idx < MM * EE; idx += 256) {
        const int m = idx >> 6, o = idx & 63;
        g_Wti[out_base + (size_t)m * (EE * EE) + o] = t[o][m];
    }
}

// ---------------------------------------------------------------------------
// Forward truncated DFT, radix-2 fold, i-vectorized (unchanged, passing)
// ---------------------------------------------------------------------------
__global__ void __launch_bounds__(128) k_fwd(const float* __restrict__ x) {
    __shared__ __align__(16) ull   s_twd[LL];
    __shared__ __align__(16) float s_u[32][EE];
    __shared__ __align__(16) float s_v[32][EE];
    const int tid = threadIdx.x;
    const int bh = blockIdx.x;
    const int b = bh >> 3, h = bh & 7;
    const int c = blockIdx.y;

    for (int i = tid; i < LL; i += 128) s_twd[i] = g_twd[i];

    const int i0 = (tid & 7) * 8;
    const int m0 = (tid >> 3) * 4;

    ull aR[4][4], aI[4][4];
    #pragma unroll
    for (int j = 0; j < 4; ++j)
        #pragma unroll
        for (int k = 0; k < 4; ++k) { aR[j][k] = 0ull; aI[j][k] = 0ull; }

    const float* xb = x + ((size_t)b * LL * HH + h) * EE;

    for (int stage = 0; stage < 8; ++stage) {
        const int lbase = c * 256 + stage * 32;
        __syncthreads();
        for (int idx4 = tid; idx4 < 32 * 16; idx4 += 128) {
            const int sl = idx4 >> 4;
            const int ii = (idx4 & 15) * 4;
            const float4 a = *(const float4*)&xb[(size_t)(lbase + sl) * (HH * EE) + ii];
            const float4 d = *(const float4*)&xb[(size_t)(lbase + sl + LHALF) * (HH * EE) + ii];
            *(float4*)&s_u[sl][ii] = make_float4(a.x + d.x, a.y + d.y, a.z + d.z, a.w + d.w);
            *(float4*)&s_v[sl][ii] = make_float4(a.x - d.x, a.y - d.y, a.z - d.z, a.w - d.w);
        }
        __syncthreads();
        #pragma unroll 2
        for (int sl = 0; sl < 32; ++sl) {
            const int l = lbase + sl;
            const ulonglong2 U0 = *(const ulonglong2*)&s_u[sl][i0];
            const ulonglong2 U1 = *(const ulonglong2*)&s_u[sl][i0 + 4];
            const ulonglong2 V0 = *(const ulonglong2*)&s_v[sl][i0];
            const ulonglong2 V1 = *(const ulonglong2*)&s_v[sl][i0 + 4];
            #pragma unroll
            for (int j = 0; j < 4; ++j) {
                const int idx = ((m0 + j) * l) & (LL - 1);
                const ull cc = s_twd[idx];
                const ull ss = s_twd[(idx + 512) & (LL - 1)];
                if (j & 1) {
                    aR[j][0] = fma2(V0.x, cc, aR[j][0]); aI[j][0] = fma2(V0.x, ss, aI[j][0]);
                    aR[j][1] = fma2(V0.y, cc, aR[j][1]); aI[j][1] = fma2(V0.y, ss, aI[j][1]);
                    aR[j][2] = fma2(V1.x, cc, aR[j][2]); aI[j][2] = fma2(V1.x, ss, aI[j][2]);
                    aR[j][3] = fma2(V1.y, cc, aR[j][3]); aI[j][3] = fma2(V1.y, ss, aI[j][3]);
                } else {
                    aR[j][0] = fma2(U0.x, cc, aR[j][0]); aI[j][0] = fma2(U0.x, ss, aI[j][0]);
                    aR[j][1] = fma2(U0.y, cc, aR[j][1]); aI[j][1] = fma2(U0.y, ss, aI[j][1]);
                    aR[j][2] = fma2(U1.x, cc, aR[j][2]); aI[j][2] = fma2(U1.x, ss, aI[j][2]);
                    aR[j][3] = fma2(U1.y, cc, aR[j][3]); aI[j][3] = fma2(U1.y, ss, aI[j][3]);
                }
            }
        }
    }

    #pragma unroll
    for (int j = 0; j < 4; ++j) {
        const size_t base = ((size_t)bh * MM + (m0 + j)) * (EE / 2) + (i0 >> 1);
        ull* pr = &g_Xpr[c][base];
        ull* pi = &g_Xpi[c][base];
        pr[0] = aR[j][0]; pr[1] = aR[j][1]; pr[2] = aR[j][2]; pr[3] = aR[j][3];
        pi[0] = aI[j][0]; pi[1] = aI[j][1]; pi[2] = aI[j][2]; pi[3] = aI[j][3];
    }
}

// ---------------------------------------------------------------------------
// Mode mixing per (m,h): reduce partials, complex GEMM over i, fold irfft
// scale, emit Y as bf16 hi/lo in B layout [bh][par][o][2j+ri] for k_invT.
// ---------------------------------------------------------------------------
__global__ void __launch_bounds__(128) k_mix() {
    __shared__ __align__(16) float sXr[BB][EE], sXi[BB][EE];
    __shared__ __align__(16) float sWr[EE][EE], sWi[EE][EE];
    const int m = blockIdx.x, h = blockIdx.y;
    const int tid = threadIdx.x;

    for (int idx = tid; idx < BB * EE / 2; idx += 128) {
        const int b = idx >> 5, ip = idx & 31;
        float xr0 = 0.f, xr1 = 0.f, xi0 = 0.f, xi1 = 0.f;
        const size_t offp = (((size_t)(b * HH + h)) * MM + m) * (EE / 2) + ip;
        #pragma unroll
        for (int cc = 0; cc < NCHUNK; ++cc) {
            const float2 r = unpack2(g_Xpr[cc][offp]);
            const float2 i2 = unpack2(g_Xpi[cc][offp]);
            xr0 += r.x; xr1 += r.y; xi0 += i2.x; xi1 += i2.y;
        }
        sXr[b][2 * ip] = xr0; sXr[b][2 * ip + 1] = xr1;
        sXi[b][2 * ip] = xi0; sXi[b][2 * ip + 1] = xi1;
    }
    const size_t wbase = ((size_t)h * MM + m) * (EE * EE);
    for (int idx = tid; idx < EE * EE; idx += 128) {
        sWr[idx >> 6][idx & 63] = g_Wtr[wbase + idx];
        sWi[idx >> 6][idx & 63] = g_Wti[wbase + idx];
    }
    __syncthreads();

    const int b = tid >> 4;
    const int o0 = (tid & 15) * 4;
    float ar0 = 0, ar1 = 0, ar2 = 0, ar3 = 0;
    float ai0 = 0, ai1 = 0, ai2 = 0, ai3 = 0;
    #pragma unroll 4
    for (int i = 0; i < EE; ++i) {
        const float xr = sXr[b][i], xi = sXi[b][i];
        const float4 w_r = *(const float4*)&sWr[i][o0];
        const float4 w_i = *(const float4*)&sWi[i][o0];
        ar0 = fmaf(xr, w_r.x, ar0); ar0 = fmaf(-xi, w_i.x, ar0);
        ai0 = fmaf(xr, w_i.x, ai0); ai0 = fmaf( xi, w_r.x, ai0);
        ar1 = fmaf(xr, w_r.y, ar1); ar1 = fmaf(-xi, w_i.y, ar1);
        ai1 = fmaf(xr, w_i.y, ai1); ai1 = fmaf( xi, w_r.y, ai1);
        ar2 = fmaf(xr, w_r.z, ar2); ar2 = fmaf(-xi, w_i.z, ar2);
        ai2 = fmaf(xr, w_i.z, ai2); ai2 = fmaf( xi, w_r.z, ai2);
        ar3 = fmaf(xr, w_r.w, ar3); ar3 = fmaf(-xi, w_i.w, ar3);
        ai3 = fmaf(xr, w_i.w, ai3); ai3 = fmaf( xi, w_r.w, ai3);
    }
    const float sc = (m == 0 ? 1.0f : 2.0f) * (1.0f / (float)LL);
    const int par = m & 1, j = m >> 1;
    const int bh = b * HH + h;
    const float vr[4] = {ar0 * sc, ar1 * sc, ar2 * sc, ar3 * sc};
    const float vi[4] = {ai0 * sc, ai1 * sc, ai2 * sc, ai3 * sc};
    #pragma unroll
    for (int t = 0; t < 4; ++t) {
        const size_t idx = (((size_t)bh * 2 + par) * 64 + (o0 + t)) * 64 + 2 * j;
        const __nv_bfloat16 hr = __float2bfloat16(vr[t]);
        g_Ybh[idx] = hr;
        g_Ybl[idx] = __float2bfloat16(vr[t] - __bfloat162float(hr));
        const __nv_bfloat16 hv = __float2bfloat16(vi[t]);
        g_Ybh[idx + 1] = hv;
        g_Ybl[idx + 1] = __float2bfloat16(vi[t] - __bfloat162float(hv));
    }
}

// ---------------------------------------------------------------------------
// Inverse DFT via mma.sync (bf16, fp32 accum), 3-product precision split:
//   E[128 l, 64 o] = Ae[128,64] · Be[64,64]^T  (K = 64 mode-re/im, even m)
//   O likewise (odd m); y_l = E+O, y_{l+1024} = E-O.
// Block (bh, l-tile of 128), 256 threads = 8 warps; warp owns 16 l-rows.
// ---------------------------------------------------------------------------
__global__ void __launch_bounds__(256) k_invT(float* __restrict__ y) {
    extern __shared__ __align__(16) char smem[];
    const uint32_t sbase = smem_to_u32(smem);
    const int tid = threadIdx.x, wid = tid >> 5, lane = tid & 31;
    const int bh = blockIdx.x, b = bh >> 3, h = bh & 7;
    const int l0 = blockIdx.y * 128;

    // Stage A tiles (128 x 64 bf16 -> 144B-padded rows)
    for (int idx = tid; idx < 1024; idx += 256) {
        const int row = idx >> 3, ch = idx & 7;
        const uint32_t d = row * ROWB + ch * 16;
        *(uint4*)(smem + OFF_AEH + d) = *((const uint4*)&g_Ah[0][(l0 + row) * 64] + ch);
        *(uint4*)(smem + OFF_AEL + d) = *((const uint4*)&g_Al[0][(l0 + row) * 64] + ch);
        *(uint4*)(smem + OFF_AOH + d) = *((const uint4*)&g_Ah[1][(l0 + row) * 64] + ch);
        *(uint4*)(smem + OFF_AOL + d) = *((const uint4*)&g_Al[1][(l0 + row) * 64] + ch);
    }
    // Stage B tiles (64 x 64 bf16)
    for (int idx = tid; idx < 512; idx += 256) {
        const int row = idx >> 3, ch = idx & 7;
        const uint32_t d = row * ROWB + ch * 16;
        const size_t sE = ((size_t)bh * 2 + 0) * 4096 + (size_t)row * 64;
        const size_t sO = ((size_t)bh * 2 + 1) * 4096 + (size_t)row * 64;
        *(uint4*)(smem + OFF_BEH + d) = *((const uint4*)&g_Ybh[sE] + ch);
        *(uint4*)(smem + OFF_BEL + d) = *((const uint4*)&g_Ybl[sE] + ch);
        *(uint4*)(smem + OFF_BOH + d) = *((const uint4*)&g_Ybh[sO] + ch);
        *(uint4*)(smem + OFF_BOL + d) = *((const uint4*)&g_Ybl[sO] + ch);
    }
    __syncthreads();

    const int m0 = wid * 16;
    float E[8][4], O[8][4];
    #pragma unroll
    for (int n = 0; n < 8; ++n)
        #pragma unroll
        for (int k = 0; k < 4; ++k) { E[n][k] = 0.f; O[n][k] = 0.f; }

    #pragma unroll
    for (int par = 0; par < 2; ++par) {
        float (*acc)[4] = par ? O : E;
        const uint32_t offAH = par ? OFF_AOH : OFF_AEH;
        const uint32_t offAL = par ? OFF_AOL : OFF_AEL;
        const uint32_t offBH = par ? OFF_BOH : OFF_BEH;
        const uint32_t offBL = par ? OFF_BOL : OFF_BEL;
        #pragma unroll
        for (int t = 0; t < 3; ++t) {
            const uint32_t offA = (t == 2) ? offAL : offAH;
            const uint32_t offB = (t == 1) ? offBL : offBH;
            #pragma unroll
            for (int s = 0; s < 4; ++s) {
                const int k0 = s * 16;
                uint32_t a0, a1, a2, a3;
                const uint32_t aaddr = sbase + offA + (m0 + (lane & 15)) * ROWB
                                     + (k0 + (lane >> 4) * 8) * 2;
                ldsm_x4(a0, a1, a2, a3, aaddr);
                const int ll = lane & 15;
                #pragma unroll
                for (int n = 0; n < 8; ++n) {
                    uint32_t b0, b1;
                    const uint32_t baddr = sbase + offB + (n * 8 + (ll & 7)) * ROWB
                                         + (k0 + (ll >> 3) * 8) * 2;
                    ldsm_x2(b0, b1, baddr);
                    mma_bf16(acc[n], a0, a1, a2, a3, b0, b1);
                }
            }
        }
    }

    // Epilogue: y_l = E+O, y_{l+1024} = E-O
    const int qr = lane >> 2, qc = (lane & 3) * 2;
    float* ybase = y + (size_t)b * LL * (HH * EE) + (size_t)h * EE;
    #pragma unroll
    for (int n = 0; n < 8; ++n) {
        const int o = n * 8 + qc;
        #pragma unroll
        for (int hr = 0; hr < 2; ++hr) {
            const int l = l0 + m0 + qr + hr * 8;
            const float e0 = E[n][2 * hr], e1 = E[n][2 * hr + 1];
            const float q0 = O[n][2 * hr], q1 = O[n][2 * hr + 1];
            *(float2*)&ybase[(size_t)l * (HH * EE) + o] = make_float2(e0 + q0, e1 + q1);
            *(float2*)&ybase[(size_t)(l + LHALF) * (HH * EE) + o] = make_float2(e0 - q0, e1 - q1);
        }
    }
}

extern "C" void kernel_launch(void* const* d_in, const int* in_sizes, int n_in,
                              void* d_out, int out_size) {
    (void)in_sizes; (void)n_in; (void)out_size;
    const float* x   = (const float*)d_in[0];
    const float* wre = (const float*)d_in[1];
    const float* wim = (const float*)d_in[2];
    float* y = (float*)d_out;

    cudaFuncSetAttribute(k_invT, cudaFuncAttributeMaxDynamicSharedMemorySize, SMEM_INV);

    k_trans<<<576, 256>>>(wre, wim);
    k_fwd<<<dim3(64, NCHUNK), 128>>>(x);
    k_mix<<<dim3(MM, HH), 128>>>();
    k_invT<<<dim3(64, 8), 256, SMEM_INV>>>(y);
}

// round 15
// speedup vs baseline: 1.6386x; 1.3492x over previous
#include <cuda_runtime.h>
#include <cuda_bf16.h>
#include <cstdint>

#define BB 8
#define LL 2048
#define HH 8
#define EE 64
#define MM 64
#define LHALF 1024

typedef unsigned long long ull;

// ---------------------------------------------------------------------------
// Device scratch (no allocation allowed)
// ---------------------------------------------------------------------------
__device__ __align__(16) float g_Wtr[HH*MM*EE*EE];             // w_real: [h][m][i][o]
__device__ __align__(16) float g_Wti[HH*MM*EE*EE];             // w_imag: [h][m][i][o]
// Forward-DFT twiddle operand: [par*2+hl][row=2j+ri][l] bf16 (A of fwd GEMM)
__device__ __align__(16) __nv_bfloat16 g_FA[4*64*1024];
// Forward output: X modes fp32, [kc][bh][m][i] (2 K-chunk partials)
__device__ __align__(16) float g_Xfr[2*64*64*64];
__device__ __align__(16) float g_Xfi[2*64*64*64];
// Inverse-DFT operands:
__device__ __align__(16) __nv_bfloat16 g_Ah[2][1024*64];       // A hi: [par][l][k=2j+ri]
__device__ __align__(16) __nv_bfloat16 g_Al[2][1024*64];       // A lo
__device__ __align__(16) __nv_bfloat16 g_Ybh[BB*HH*2*64*64];   // B hi: [bh][par][o][k]
__device__ __align__(16) __nv_bfloat16 g_Ybl[BB*HH*2*64*64];   // B lo

__device__ __forceinline__ uint32_t smem_to_u32(const void* p) {
    uint32_t a;
    asm("{ .reg .u64 t; cvta.to.shared.u64 t, %1; cvt.u32.u64 %0, t; }" : "=r"(a) : "l"(p));
    return a;
}
__device__ __forceinline__ void ldsm_x4(uint32_t& r0, uint32_t& r1, uint32_t& r2, uint32_t& r3,
                                        uint32_t a) {
    asm volatile("ldmatrix.sync.aligned.m8n8.x4.shared.b16 {%0,%1,%2,%3}, [%4];"
                 : "=r"(r0), "=r"(r1), "=r"(r2), "=r"(r3) : "r"(a));
}
__device__ __forceinline__ void ldsm_x2(uint32_t& r0, uint32_t& r1, uint32_t a) {
    asm volatile("ldmatrix.sync.aligned.m8n8.x2.shared.b16 {%0,%1}, [%2];"
                 : "=r"(r0), "=r"(r1) : "r"(a));
}
__device__ __forceinline__ void ldsm_x2t(uint32_t& r0, uint32_t& r1, uint32_t a) {
    asm volatile("ldmatrix.sync.aligned.m8n8.x2.trans.shared.b16 {%0,%1}, [%2];"
                 : "=r"(r0), "=r"(r1) : "r"(a));
}
__device__ __forceinline__ void mma_bf16(float* c, uint32_t a0, uint32_t a1, uint32_t a2,
                                         uint32_t a3, uint32_t b0, uint32_t b1) {
    asm volatile("mma.sync.aligned.m16n8k16.row.col.f32.bf16.bf16.f32 "
                 "{%0,%1,%2,%3}, {%4,%5,%6,%7}, {%8,%9}, {%0,%1,%2,%3};"
                 : "+f"(c[0]), "+f"(c[1]), "+f"(c[2]), "+f"(c[3])
                 : "r"(a0), "r"(a1), "r"(a2), "r"(a3), "r"(b0), "r"(b1));
}
// Split v into bf16 hi + lo pairs and store 4 elems (8B each of hi/lo)
__device__ __forceinline__ void split_store4(char* ph, char* pl, float4 u) {
    const __nv_bfloat162 h0 = __floats2bfloat162_rn(u.x, u.y);
    const __nv_bfloat162 h1 = __floats2bfloat162_rn(u.z, u.w);
    const float2 f0 = __bfloat1622float2(h0);
    const float2 f1 = __bfloat1622float2(h1);
    const __nv_bfloat162 l0 = __floats2bfloat162_rn(u.x - f0.x, u.y - f0.y);
    const __nv_bfloat162 l1 = __floats2bfloat162_rn(u.z - f1.x, u.w - f1.y);
    *(__nv_bfloat162*)(ph) = h0;     *(__nv_bfloat162*)(ph + 4) = h1;
    *(__nv_bfloat162*)(pl) = l0;     *(__nv_bfloat162*)(pl + 4) = l1;
}

// Padded-row tile geometry (144B rows: conflict-free ldmatrix, 16B-aligned)
#define ROWB 144
#define TILE_A (128 * ROWB)
#define TILE_B (64 * ROWB)
// Inverse kernel smem
#define OFF_AEH 0
#define OFF_AEL (OFF_AEH + TILE_A)
#define OFF_AOH (OFF_AEL + TILE_A)
#define OFF_AOL (OFF_AOH + TILE_A)
#define OFF_BEH (OFF_AOL + TILE_A)
#define OFF_BEL (OFF_BEH + TILE_B)
#define OFF_BOH (OFF_BEL + TILE_B)
#define OFF_BOL (OFF_BOH + TILE_B)
#define SMEM_INV (OFF_BOL + TILE_B)
// Forward kernel smem: 4 A tiles (par x hi/lo) + uh/ul/vh/vl, all 64x64
#define FT 9216                      // 64 * ROWB
#define OFF_FA 0                     // + t*FT, t = par*2+hl
#define OFF_FU (4 * FT)              // + t*FT, t: 0=uh 1=ul 2=vh 3=vl
#define SMEM_FWD (8 * FT)            // 73,728 B

// ---------------------------------------------------------------------------
// Setup: W transpose (blocks 0-511), inverse A gen (512-575), fwd A gen (576-639)
// ---------------------------------------------------------------------------
__global__ void __launch_bounds__(256) k_trans(const float* __restrict__ wre,
                                               const float* __restrict__ wim) {
    const int tid = threadIdx.x;

    if (blockIdx.x >= 576) {
        // Forward twiddle rows: block handles row r for both parities, all l.
        const int r = blockIdx.x - 576;          // 0..63
        const int j = r >> 1, ri = r & 1;
        for (int idx = tid; idx < 2048; idx += 256) {
            const int par = idx >> 10, l = idx & 1023;
            const int m = 2 * j + par;
            const int ang = (m * l) & (LL - 1);
            float s, c;
            sincospif((float)ang * (1.0f / 1024.0f), &s, &c);
            const float v = ri ? -s : c;
            const __nv_bfloat16 hi = __float2bfloat16(v);
            g_FA[((size_t)(par * 2 + 0) * 64 + r) * 1024 + l] = hi;
            g_FA[((size_t)(par * 2 + 1) * 64 + r) * 1024 + l] =
                __float2bfloat16(v - __bfloat162float(hi));
        }
        return;
    }
    if (blockIdx.x >= 512) {
        // Inverse A: blocks 512..575, 16 l-rows each
        const int l0 = (blockIdx.x - 512) * 16;
        for (int idx = tid; idx < 16 * 128; idx += 256) {
            const int l = l0 + (idx >> 7);
            const int rem = idx & 127;
            const int par = rem >> 6;
            const int kk = rem & 63;
            const int m = ((kk >> 1) << 1) + par;
            const int ri = kk & 1;
            const int ang = (m * l) & (LL - 1);
            float s, c;
            sincospif((float)ang * (1.0f / 1024.0f), &s, &c);
            const float v = ri ? -s : c;
            const __nv_bfloat16 hi = __float2bfloat16(v);
            g_Ah[par][l * 64 + kk] = hi;
            g_Al[par][l * 64 + kk] = __float2bfloat16(v - __bfloat162float(hi));
        }
        return;
    }

    __shared__ float t[EE][EE + 1];
    const int h = blockIdx.x >> 6;
    const int i = blockIdx.x & 63;
    const size_t in_base = (size_t)blockIdx.x * (EE * MM);
    const size_t out_base = (size_t)h * (MM * EE * EE) + (size_t)i * EE;

    for (int idx = tid; idx < EE * MM; idx += 256) t[idx >> 6][idx & 63] = wre[in_base + idx];
    __syncthreads();
    for (int idx = tid; idx < MM * EE; idx += 256) {
        const int m = idx >> 6, o = idx & 63;
        g_Wtr[out_base + (size_t)m * (EE * EE) + o] = t[o][m];
    }
    __syncthreads();
    for (int idx = tid; idx < EE * MM; idx += 256) t[idx >> 6][idx & 63] = wim[in_base + idx];
    __syncthreads();
    for (int idx = tid; idx < MM * EE; idx += 256) {
        const int m = idx >> 6, o = idx & 63;
        g_Wti[out_base + (size_t)m * (EE * EE) + o] = t[o][m];
    }
}

// ---------------------------------------------------------------------------
// Forward DFT via mma.sync: per (bh, kc): for each parity p,
//   D[64 rows (2j+ri), 64 i] += A_p[rows, K] · B_p[K, i],  K = 512 l (kc half)
// B_p = radix-2 folded x (u for even m, v for odd), staged bf16 hi/lo, loaded
// with ldmatrix.trans from [l][i] storage. 3-product precision split.
// Block 256 thr = 8 warps; warps 0-3: parity 0 rows 16w.. ; warps 4-7: parity 1.
// ---------------------------------------------------------------------------
__global__ void __launch_bounds__(256) k_fwdT(const float* __restrict__ x) {
    extern __shared__ __align__(16) char smem[];
    const uint32_t sbase = smem_to_u32(smem);
    const int tid = threadIdx.x, wid = tid >> 5, lane = tid & 31;
    const int bh = blockIdx.x, b = bh >> 3, h = bh & 7;
    const int kc = blockIdx.y;

    const int p = wid >> 2;            // parity this warp computes
    const int m0 = (wid & 3) * 16;     // row block within parity

    float C[8][4];
    #pragma unroll
    for (int n = 0; n < 8; ++n)
        #pragma unroll
        for (int k = 0; k < 4; ++k) C[n][k] = 0.f;

    const float* xb = x + ((size_t)b * LL * HH + h) * EE;

    for (int stage = 0; stage < 8; ++stage) {
        const int l0 = kc * 512 + stage * 64;
        __syncthreads();
        // Stage folded x -> uh/ul/vh/vl tiles [64 l][64 i]
        for (int idx = tid; idx < 64 * 16; idx += 256) {
            const int sl = idx >> 4;
            const int ii = (idx & 15) * 4;
            const float4 a = *(const float4*)&xb[(size_t)(l0 + sl) * (HH * EE) + ii];
            const float4 d = *(const float4*)&xb[(size_t)(l0 + sl + LHALF) * (HH * EE) + ii];
            const float4 u = make_float4(a.x + d.x, a.y + d.y, a.z + d.z, a.w + d.w);
            const float4 v = make_float4(a.x - d.x, a.y - d.y, a.z - d.z, a.w - d.w);
            const int off = sl * ROWB + ii * 2;
            split_store4(smem + OFF_FU + 0 * FT + off, smem + OFF_FU + 1 * FT + off, u);
            split_store4(smem + OFF_FU + 2 * FT + off, smem + OFF_FU + 3 * FT + off, v);
        }
        // Stage A tiles (4 x [64 rows][64 k] bf16)
        for (int idx = tid; idx < 2048; idx += 256) {
            const int t = idx >> 9;
            const int row = (idx >> 3) & 63;
            const int ch = idx & 7;
            const uint4 val = *(const uint4*)&g_FA[((size_t)t * 64 + row) * 1024 + l0 + ch * 8];
            *(uint4*)(smem + OFF_FA + t * FT + row * ROWB + ch * 16) = val;
        }
        __syncthreads();

        const uint32_t offAH = sbase + OFF_FA + (p * 2 + 0) * FT;
        const uint32_t offAL = sbase + OFF_FA + (p * 2 + 1) * FT;
        const uint32_t offBH = sbase + OFF_FU + (p * 2 + 0) * FT;   // uh or vh
        const uint32_t offBL = offBH + FT;                           // ul or vl
        #pragma unroll
        for (int s4 = 0; s4 < 4; ++s4) {
            const int k0 = s4 * 16;
            const uint32_t aoff = (m0 + (lane & 15)) * ROWB + (k0 + (lane >> 4) * 8) * 2;
            uint32_t ah0, ah1, ah2, ah3, al0, al1, al2, al3;
            ldsm_x4(ah0, ah1, ah2, ah3, offAH + aoff);
            ldsm_x4(al0, al1, al2, al3, offAL + aoff);
            const int ll = lane & 15;
            const uint32_t brow = (uint32_t)(k0 + (ll & 7) + 8 * (ll >> 3)) * ROWB;
            #pragma unroll
            for (int n = 0; n < 8; ++n) {
                uint32_t bh0, bh1, bl0, bl1;
                ldsm_x2t(bh0, bh1, offBH + brow + n * 16);
                ldsm_x2t(bl0, bl1, offBL + brow + n * 16);
                mma_bf16(C[n], ah0, ah1, ah2, ah3, bh0, bh1);
                mma_bf16(C[n], ah0, ah1, ah2, ah3, bl0, bl1);
                mma_bf16(C[n], al0, al1, al2, al3, bh0, bh1);
            }
        }
    }

    // Epilogue: row r = m0+qr+8*hr -> mode m = 2*(r>>1)+p, ri = r&1
    const int qr = lane >> 2, qc = (lane & 3) * 2;
    #pragma unroll
    for (int n = 0; n < 8; ++n) {
        const int i = n * 8 + qc;
        #pragma unroll
        for (int hr = 0; hr < 2; ++hr) {
            const int r = m0 + qr + hr * 8;
            const int m = 2 * (r >> 1) + p;
            float* dst = ((r & 1) ? g_Xfi : g_Xfr)
                       + (((size_t)kc * 64 + bh) * 64 + m) * 64 + i;
            *(float2*)dst = make_float2(C[n][2 * hr], C[n][2 * hr + 1]);
        }
    }
}

// ---------------------------------------------------------------------------
// Mode mixing per (m,h): sum 2 K-chunk partials, complex GEMM over i, fold
// irfft scale, emit Y bf16 hi/lo in [bh][par][o][2j+ri] for k_invT.
// ---------------------------------------------------------------------------
__global__ void __launch_bounds__(128) k_mix() {
    __shared__ __align__(16) float sXr[BB][EE], sXi[BB][EE];
    __shared__ __align__(16) float sWr[EE][EE], sWi[EE][EE];
    const int m = blockIdx.x, h = blockIdx.y;
    const int tid = threadIdx.x;
    const size_t KCS = (size_t)64 * 64 * 64;

    for (int idx = tid; idx < BB * EE; idx += 128) {
        const int b = idx >> 6, i = idx & 63;
        const size_t off = (((size_t)(b * HH + h)) * 64 + m) * 64 + i;
        sXr[b][i] = g_Xfr[off] + g_Xfr[off + KCS];
        sXi[b][i] = g_Xfi[off] + g_Xfi[off + KCS];
    }
    const size_t wbase = ((size_t)h * MM + m) * (EE * EE);
    for (int idx = tid; idx < EE * EE; idx += 128) {
        sWr[idx >> 6][idx & 63] = g_Wtr[wbase + idx];
        sWi[idx >> 6][idx & 63] = g_Wti[wbase + idx];
    }
    __syncthreads();

    const int b = tid >> 4;
    const int o0 = (tid & 15) * 4;
    float ar0 = 0, ar1 = 0, ar2 = 0, ar3 = 0;
    float ai0 = 0, ai1 = 0, ai2 = 0, ai3 = 0;
    #pragma unroll 4
    for (int i = 0; i < EE; ++i) {
        const float xr = sXr[b][i], xi = sXi[b][i];
        const float4 w_r = *(const float4*)&sWr[i][o0];
        const float4 w_i = *(const float4*)&sWi[i][o0];
        ar0 = fmaf(xr, w_r.x, ar0); ar0 = fmaf(-xi, w_i.x, ar0);
        ai0 = fmaf(xr, w_i.x, ai0); ai0 = fmaf( xi, w_r.x, ai0);
        ar1 = fmaf(xr, w_r.y, ar1); ar1 = fmaf(-xi, w_i.y, ar1);
        ai1 = fmaf(xr, w_i.y, ai1); ai1 = fmaf( xi, w_r.y, ai1);
        ar2 = fmaf(xr, w_r.z, ar2); ar2 = fmaf(-xi, w_i.z, ar2);
        ai2 = fmaf(xr, w_i.z, ai2); ai2 = fmaf( xi, w_r.z, ai2);
        ar3 = fmaf(xr, w_r.w, ar3); ar3 = fmaf(-xi, w_i.w, ar3);
        ai3 = fmaf(xr, w_i.w, ai3); ai3 = fmaf( xi, w_r.w, ai3);
    }
    const float sc = (m == 0 ? 1.0f : 2.0f) * (1.0f / (float)LL);
    const int par = m & 1, j = m >> 1;
    const int bh = b * HH + h;
    const float vr[4] = {ar0 * sc, ar1 * sc, ar2 * sc, ar3 * sc};
    const float vi[4] = {ai0 * sc, ai1 * sc, ai2 * sc, ai3 * sc};
    #pragma unroll
    for (int t = 0; t < 4; ++t) {
        const size_t idx = (((size_t)bh * 2 + par) * 64 + (o0 + t)) * 64 + 2 * j;
        const __nv_bfloat16 hr = __float2bfloat16(vr[t]);
        g_Ybh[idx] = hr;
        g_Ybl[idx] = __float2bfloat16(vr[t] - __bfloat162float(hr));
        const __nv_bfloat16 hv = __float2bfloat16(vi[t]);
        g_Ybh[idx + 1] = hv;
        g_Ybl[idx + 1] = __float2bfloat16(vi[t] - __bfloat162float(hv));
    }
}

// ---------------------------------------------------------------------------
// Inverse DFT via mma.sync (unchanged from round 14, passing):
//   E[128 l, 64 o] = Ae · Be^T, O likewise; y_l = E+O, y_{l+1024} = E-O.
// ---------------------------------------------------------------------------
__global__ void __launch_bounds__(256) k_invT(float* __restrict__ y) {
    extern __shared__ __align__(16) char smem[];
    const uint32_t sbase = smem_to_u32(smem);
    const int tid = threadIdx.x, wid = tid >> 5, lane = tid & 31;
    const int bh = blockIdx.x, b = bh >> 3, h = bh & 7;
    const int l0 = blockIdx.y * 128;

    for (int idx = tid; idx < 1024; idx += 256) {
        const int row = idx >> 3, ch = idx & 7;
        const uint32_t d = row * ROWB + ch * 16;
        *(uint4*)(smem + OFF_AEH + d) = *((const uint4*)&g_Ah[0][(l0 + row) * 64] + ch);
        *(uint4*)(smem + OFF_AEL + d) = *((const uint4*)&g_Al[0][(l0 + row) * 64] + ch);
        *(uint4*)(smem + OFF_AOH + d) = *((const uint4*)&g_Ah[1][(l0 + row) * 64] + ch);
        *(uint4*)(smem + OFF_AOL + d) = *((const uint4*)&g_Al[1][(l0 + row) * 64] + ch);
    }
    for (int idx = tid; idx < 512; idx += 256) {
        const int row = idx >> 3, ch = idx & 7;
        const uint32_t d = row * ROWB + ch * 16;
        const size_t sE = ((size_t)bh * 2 + 0) * 4096 + (size_t)row * 64;
        const size_t sO = ((size_t)bh * 2 + 1) * 4096 + (size_t)row * 64;
        *(uint4*)(smem + OFF_BEH + d) = *((const uint4*)&g_Ybh[sE] + ch);
        *(uint4*)(smem + OFF_BEL + d) = *((const uint4*)&g_Ybl[sE] + ch);
        *(uint4*)(smem + OFF_BOH + d) = *((const uint4*)&g_Ybh[sO] + ch);
        *(uint4*)(smem + OFF_BOL + d) = *((const uint4*)&g_Ybl[sO] + ch);
    }
    __syncthreads();

    const int m0 = wid * 16;
    float E[8][4], O[8][4];
    #pragma unroll
    for (int n = 0; n < 8; ++n)
        #pragma unroll
        for (int k = 0; k < 4; ++k) { E[n][k] = 0.f; O[n][k] = 0.f; }

    #pragma unroll
    for (int par = 0; par < 2; ++par) {
        float (*acc)[4] = par ? O : E;
        const uint32_t offAH = par ? OFF_AOH : OFF_AEH;
        const uint32_t offAL = par ? OFF_AOL : OFF_AEL;
        const uint32_t offBH = par ? OFF_BOH : OFF_BEH;
        const uint32_t offBL = par ? OFF_BOL : OFF_BEL;
        #pragma unroll
        for (int t = 0; t < 3; ++t) {
            const uint32_t offA = (t == 2) ? offAL : offAH;
            const uint32_t offB = (t == 1) ? offBL : offBH;
            #pragma unroll
            for (int s = 0; s < 4; ++s) {
                const int k0 = s * 16;
                uint32_t a0, a1, a2, a3;
                const uint32_t aaddr = sbase + offA + (m0 + (lane & 15)) * ROWB
                                     + (k0 + (lane >> 4) * 8) * 2;
                ldsm_x4(a0, a1, a2, a3, aaddr);
                const int ll = lane & 15;
                #pragma unroll
                for (int n = 0; n < 8; ++n) {
                    uint32_t b0, b1;
                    const uint32_t baddr = sbase + offB + (n * 8 + (ll & 7)) * ROWB
                                         + (k0 + (ll >> 3) * 8) * 2;
                    ldsm_x2(b0, b1, baddr);
                    mma_bf16(acc[n], a0, a1, a2, a3, b0, b1);
                }
            }
        }
    }

    const int qr = lane >> 2, qc = (lane & 3) * 2;
    float* ybase = y + (size_t)b * LL * (HH * EE) + (size_t)h * EE;
    #pragma unroll
    for (int n = 0; n < 8; ++n) {
        const int o = n * 8 + qc;
        #pragma unroll
        for (int hr = 0; hr < 2; ++hr) {
            const int l = l0 + m0 + qr + hr * 8;
            const float e0 = E[n][2 * hr], e1 = E[n][2 * hr + 1];
            const float q0 = O[n][2 * hr], q1 = O[n][2 * hr + 1];
            *(float2*)&ybase[(size_t)l * (HH * EE) + o] = make_float2(e0 + q0, e1 + q1);
            *(float2*)&ybase[(size_t)(l + LHALF) * (HH * EE) + o] = make_float2(e0 - q0, e1 - q1);
        }
    }
}

extern "C" void kernel_launch(void* const* d_in, const int* in_sizes, int n_in,
                              void* d_out, int out_size) {
    (void)in_sizes; (void)n_in; (void)out_size;
    const float* x   = (const float*)d_in[0];
    const float* wre = (const float*)d_in[1];
    const float* wim = (const float*)d_in[2];
    float* y = (float*)d_out;

    cudaFuncSetAttribute(k_fwdT, cudaFuncAttributeMaxDynamicSharedMemorySize, SMEM_FWD);
    cudaFuncSetAttribute(k_invT, cudaFuncAttributeMaxDynamicSharedMemorySize, SMEM_INV);

    k_trans<<<640, 256>>>(wre, wim);
    k_fwdT<<<dim3(64, 2), 256, SMEM_FWD>>>(x);
    k_mix<<<dim3(MM, HH), 128>>>();
    k_invT<<<dim3(64, 8), 256, SMEM_INV>>>(y);
}

// round 16
// speedup vs baseline: 2.0438x; 1.2473x over previous
#include <cuda_runtime.h>
#include <cuda_bf16.h>
#include <cstdint>

#define BB 8
#define LL 2048
#define HH 8
#define EE 64
#define MM 64
#define LHALF 1024
#define NKC 4

typedef unsigned long long ull;

// ---------------------------------------------------------------------------
// Device scratch (no allocation allowed)
// ---------------------------------------------------------------------------
__device__ __align__(16) float g_Wtr[HH*MM*EE*EE];             // w_real: [h][m][i][o]
__device__ __align__(16) float g_Wti[HH*MM*EE*EE];             // w_imag: [h][m][i][o]
// Forward-DFT twiddle operand: [par*2+hl][row=2j+ri][l] bf16 (A of fwd GEMM)
__device__ __align__(16) __nv_bfloat16 g_FA[4*64*1024];
// Forward output: X modes fp32, [kc][bh][m][i] (NKC K-chunk partials)
__device__ __align__(16) float g_Xfr[NKC*64*64*64];
__device__ __align__(16) float g_Xfi[NKC*64*64*64];
// Inverse-DFT operands:
__device__ __align__(16) __nv_bfloat16 g_Ah[2][1024*64];       // A hi: [par][l][k=2j+ri]
__device__ __align__(16) __nv_bfloat16 g_Al[2][1024*64];       // A lo
__device__ __align__(16) __nv_bfloat16 g_Ybh[BB*HH*2*64*64];   // B hi: [bh][par][o][k]
__device__ __align__(16) __nv_bfloat16 g_Ybl[BB*HH*2*64*64];   // B lo

__device__ __forceinline__ uint32_t smem_to_u32(const void* p) {
    uint32_t a;
    asm("{ .reg .u64 t; cvta.to.shared.u64 t, %1; cvt.u32.u64 %0, t; }" : "=r"(a) : "l"(p));
    return a;
}
__device__ __forceinline__ void ldsm_x4(uint32_t& r0, uint32_t& r1, uint32_t& r2, uint32_t& r3,
                                        uint32_t a) {
    asm volatile("ldmatrix.sync.aligned.m8n8.x4.shared.b16 {%0,%1,%2,%3}, [%4];"
                 : "=r"(r0), "=r"(r1), "=r"(r2), "=r"(r3) : "r"(a));
}
__device__ __forceinline__ void ldsm_x2(uint32_t& r0, uint32_t& r1, uint32_t a) {
    asm volatile("ldmatrix.sync.aligned.m8n8.x2.shared.b16 {%0,%1}, [%2];"
                 : "=r"(r0), "=r"(r1) : "r"(a));
}
__device__ __forceinline__ void ldsm_x2t(uint32_t& r0, uint32_t& r1, uint32_t a) {
    asm volatile("ldmatrix.sync.aligned.m8n8.x2.trans.shared.b16 {%0,%1}, [%2];"
                 : "=r"(r0), "=r"(r1) : "r"(a));
}
__device__ __forceinline__ void mma_bf16(float* c, uint32_t a0, uint32_t a1, uint32_t a2,
                                         uint32_t a3, uint32_t b0, uint32_t b1) {
    asm volatile("mma.sync.aligned.m16n8k16.row.col.f32.bf16.bf16.f32 "
                 "{%0,%1,%2,%3}, {%4,%5,%6,%7}, {%8,%9}, {%0,%1,%2,%3};"
                 : "+f"(c[0]), "+f"(c[1]), "+f"(c[2]), "+f"(c[3])
                 : "r"(a0), "r"(a1), "r"(a2), "r"(a3), "r"(b0), "r"(b1));
}
__device__ __forceinline__ void split_store4(char* ph, char* pl, float4 u) {
    const __nv_bfloat162 h0 = __floats2bfloat162_rn(u.x, u.y);
    const __nv_bfloat162 h1 = __floats2bfloat162_rn(u.z, u.w);
    const float2 f0 = __bfloat1622float2(h0);
    const float2 f1 = __bfloat1622float2(h1);
    const __nv_bfloat162 l0 = __floats2bfloat162_rn(u.x - f0.x, u.y - f0.y);
    const __nv_bfloat162 l1 = __floats2bfloat162_rn(u.z - f1.x, u.w - f1.y);
    *(__nv_bfloat162*)(ph) = h0;     *(__nv_bfloat162*)(ph + 4) = h1;
    *(__nv_bfloat162*)(pl) = l0;     *(__nv_bfloat162*)(pl + 4) = l1;
}

// Padded-row tile geometry (144B rows: conflict-free ldmatrix, 16B-aligned)
#define ROWB 144
#define TILE_A (128 * ROWB)
#define TILE_B2 (32 * ROWB)
// Inverse kernel smem (A full l-tile; B split to 32-o half)
#define OFF_AEH 0
#define OFF_AEL (OFF_AEH + TILE_A)
#define OFF_AOH (OFF_AEL + TILE_A)
#define OFF_AOL (OFF_AOH + TILE_A)
#define OFF_BEH (OFF_AOL + TILE_A)
#define OFF_BEL (OFF_BEH + TILE_B2)
#define OFF_BOH (OFF_BEL + TILE_B2)
#define OFF_BOL (OFF_BOH + TILE_B2)
#define SMEM_INV (OFF_BOL + TILE_B2)   // 92,160 B
// Forward kernel smem: 4 A tiles (par x hi/lo) + uh/ul/vh/vl, all 64x64
#define FT 9216                        // 64 * ROWB
#define OFF_FA 0
#define OFF_FU (4 * FT)
#define SMEM_FWD (8 * FT)              // 73,728 B

// ---------------------------------------------------------------------------
// Setup: W transpose (blocks 0-511), inverse A gen (512-575), fwd A gen (576-639)
// ---------------------------------------------------------------------------
__global__ void __launch_bounds__(256) k_trans(const float* __restrict__ wre,
                                               const float* __restrict__ wim) {
    const int tid = threadIdx.x;

    if (blockIdx.x >= 576) {
        const int r = blockIdx.x - 576;          // 0..63
        const int j = r >> 1, ri = r & 1;
        for (int idx = tid; idx < 2048; idx += 256) {
            const int par = idx >> 10, l = idx & 1023;
            const int m = 2 * j + par;
            const int ang = (m * l) & (LL - 1);
            float s, c;
            sincospif((float)ang * (1.0f / 1024.0f), &s, &c);
            const float v = ri ? -s : c;
            const __nv_bfloat16 hi = __float2bfloat16(v);
            g_FA[((size_t)(par * 2 + 0) * 64 + r) * 1024 + l] = hi;
            g_FA[((size_t)(par * 2 + 1) * 64 + r) * 1024 + l] =
                __float2bfloat16(v - __bfloat162float(hi));
        }
        return;
    }
    if (blockIdx.x >= 512) {
        const int l0 = (blockIdx.x - 512) * 16;
        for (int idx = tid; idx < 16 * 128; idx += 256) {
            const int l = l0 + (idx >> 7);
            const int rem = idx & 127;
            const int par = rem >> 6;
            const int kk = rem & 63;
            const int m = ((kk >> 1) << 1) + par;
            const int ri = kk & 1;
            const int ang = (m * l) & (LL - 1);
            float s, c;
            sincospif((float)ang * (1.0f / 1024.0f), &s, &c);
            const float v = ri ? -s : c;
            const __nv_bfloat16 hi = __float2bfloat16(v);
            g_Ah[par][l * 64 + kk] = hi;
            g_Al[par][l * 64 + kk] = __float2bfloat16(v - __bfloat162float(hi));
        }
        return;
    }

    __shared__ float t[EE][EE + 1];
    const int h = blockIdx.x >> 6;
    const int i = blockIdx.x & 63;
    const size_t in_base = (size_t)blockIdx.x * (EE * MM);
    const size_t out_base = (size_t)h * (MM * EE * EE) + (size_t)i * EE;

    for (int idx = tid; idx < EE * MM; idx += 256) t[idx >> 6][idx & 63] = wre[in_base + idx];
    __syncthreads();
    for (int idx = tid; idx < MM * EE; idx += 256) {
        const int m = idx >> 6, o = idx & 63;
        g_Wtr[out_base + (size_t)m * (EE * EE) + o] = t[o][m];
    }
    __syncthreads();
    for (int idx = tid; idx < EE * MM; idx += 256) t[idx >> 6][idx & 63] = wim[in_base + idx];
    __syncthreads();
    for (int idx = tid; idx < MM * EE; idx += 256) {
        const int m = idx >> 6, o = idx & 63;
        g_Wti[out_base + (size_t)m * (EE * EE) + o] = t[o][m];
    }
}

// ---------------------------------------------------------------------------
// Forward DFT via mma.sync, grid (bh=64, kc=4): per parity p,
//   D[64 rows, 64 i] += A_p[rows, 256 l] · B_p[256 l, i]  (4 stages of 64 l)
// ---------------------------------------------------------------------------
__global__ void __launch_bounds__(256) k_fwdT(const float* __restrict__ x) {
    extern __shared__ __align__(16) char smem[];
    const uint32_t sbase = smem_to_u32(smem);
    const int tid = threadIdx.x, wid = tid >> 5, lane = tid & 31;
    const int bh = blockIdx.x, b = bh >> 3, h = bh & 7;
    const int kc = blockIdx.y;

    const int p = wid >> 2;            // parity this warp computes
    const int m0 = (wid & 3) * 16;     // row block within parity

    float C[8][4];
    #pragma unroll
    for (int n = 0; n < 8; ++n)
        #pragma unroll
        for (int k = 0; k < 4; ++k) C[n][k] = 0.f;

    const float* xb = x + ((size_t)b * LL * HH + h) * EE;

    for (int stage = 0; stage < 4; ++stage) {
        const int l0 = kc * 256 + stage * 64;
        __syncthreads();
        // Stage folded x -> uh/ul/vh/vl tiles [64 l][64 i]
        for (int idx = tid; idx < 64 * 16; idx += 256) {
            const int sl = idx >> 4;
            const int ii = (idx & 15) * 4;
            const float4 a = *(const float4*)&xb[(size_t)(l0 + sl) * (HH * EE) + ii];
            const float4 d = *(const float4*)&xb[(size_t)(l0 + sl + LHALF) * (HH * EE) + ii];
            const float4 u = make_float4(a.x + d.x, a.y + d.y, a.z + d.z, a.w + d.w);
            const float4 v = make_float4(a.x - d.x, a.y - d.y, a.z - d.z, a.w - d.w);
            const int off = sl * ROWB + ii * 2;
            split_store4(smem + OFF_FU + 0 * FT + off, smem + OFF_FU + 1 * FT + off, u);
            split_store4(smem + OFF_FU + 2 * FT + off, smem + OFF_FU + 3 * FT + off, v);
        }
        // Stage A tiles (4 x [64 rows][64 k] bf16)
        for (int idx = tid; idx < 2048; idx += 256) {
            const int t = idx >> 9;
            const int row = (idx >> 3) & 63;
            const int ch = idx & 7;
            const uint4 val = *(const uint4*)&g_FA[((size_t)t * 64 + row) * 1024 + l0 + ch * 8];
            *(uint4*)(smem + OFF_FA + t * FT + row * ROWB + ch * 16) = val;
        }
        __syncthreads();

        const uint32_t offAH = sbase + OFF_FA + (p * 2 + 0) * FT;
        const uint32_t offAL = sbase + OFF_FA + (p * 2 + 1) * FT;
        const uint32_t offBH = sbase + OFF_FU + (p * 2 + 0) * FT;
        const uint32_t offBL = offBH + FT;
        #pragma unroll
        for (int s4 = 0; s4 < 4; ++s4) {
            const int k0 = s4 * 16;
            const uint32_t aoff = (m0 + (lane & 15)) * ROWB + (k0 + (lane >> 4) * 8) * 2;
            uint32_t ah0, ah1, ah2, ah3, al0, al1, al2, al3;
            ldsm_x4(ah0, ah1, ah2, ah3, offAH + aoff);
            ldsm_x4(al0, al1, al2, al3, offAL + aoff);
            const int ll = lane & 15;
            const uint32_t brow = (uint32_t)(k0 + (ll & 7) + 8 * (ll >> 3)) * ROWB;
            #pragma unroll
            for (int n = 0; n < 8; ++n) {
                uint32_t bh0, bh1, bl0, bl1;
                ldsm_x2t(bh0, bh1, offBH + brow + n * 16);
                ldsm_x2t(bl0, bl1, offBL + brow + n * 16);
                mma_bf16(C[n], ah0, ah1, ah2, ah3, bh0, bh1);
                mma_bf16(C[n], ah0, ah1, ah2, ah3, bl0, bl1);
                mma_bf16(C[n], al0, al1, al2, al3, bh0, bh1);
            }
        }
    }

    // Epilogue: row r = m0+qr+8*hr -> mode m = 2*(r>>1)+p, ri = r&1
    const int qr = lane >> 2, qc = (lane & 3) * 2;
    #pragma unroll
    for (int n = 0; n < 8; ++n) {
        const int i = n * 8 + qc;
        #pragma unroll
        for (int hr = 0; hr < 2; ++hr) {
            const int r = m0 + qr + hr * 8;
            const int m = 2 * (r >> 1) + p;
            float* dst = ((r & 1) ? g_Xfi : g_Xfr)
                       + (((size_t)kc * 64 + bh) * 64 + m) * 64 + i;
            *(float2*)dst = make_float2(C[n][2 * hr], C[n][2 * hr + 1]);
        }
    }
}

// ---------------------------------------------------------------------------
// Mode mixing per (m,h): sum NKC K-chunk partials, complex GEMM over i, fold
// irfft scale, emit Y bf16 hi/lo in [bh][par][o][2j+ri] for k_invT.
// ---------------------------------------------------------------------------
__global__ void __launch_bounds__(128) k_mix() {
    __shared__ __align__(16) float sXr[BB][EE], sXi[BB][EE];
    __shared__ __align__(16) float sWr[EE][EE], sWi[EE][EE];
    const int m = blockIdx.x, h = blockIdx.y;
    const int tid = threadIdx.x;
    const size_t KCS = (size_t)64 * 64 * 64;

    for (int idx = tid; idx < BB * EE; idx += 128) {
        const int b = idx >> 6, i = idx & 63;
        const size_t off = (((size_t)(b * HH + h)) * 64 + m) * 64 + i;
        float xr = 0.f, xi = 0.f;
        #pragma unroll
        for (int cc = 0; cc < NKC; ++cc) {
            xr += g_Xfr[off + cc * KCS];
            xi += g_Xfi[off + cc * KCS];
        }
        sXr[b][i] = xr; sXi[b][i] = xi;
    }
    const size_t wbase = ((size_t)h * MM + m) * (EE * EE);
    for (int idx = tid; idx < EE * EE; idx += 128) {
        sWr[idx >> 6][idx & 63] = g_Wtr[wbase + idx];
        sWi[idx >> 6][idx & 63] = g_Wti[wbase + idx];
    }
    __syncthreads();

    const int b = tid >> 4;
    const int o0 = (tid & 15) * 4;
    float ar0 = 0, ar1 = 0, ar2 = 0, ar3 = 0;
    float ai0 = 0, ai1 = 0, ai2 = 0, ai3 = 0;
    #pragma unroll 4
    for (int i = 0; i < EE; ++i) {
        const float xr = sXr[b][i], xi = sXi[b][i];
        const float4 w_r = *(const float4*)&sWr[i][o0];
        const float4 w_i = *(const float4*)&sWi[i][o0];
        ar0 = fmaf(xr, w_r.x, ar0); ar0 = fmaf(-xi, w_i.x, ar0);
        ai0 = fmaf(xr, w_i.x, ai0); ai0 = fmaf( xi, w_r.x, ai0);
        ar1 = fmaf(xr, w_r.y, ar1); ar1 = fmaf(-xi, w_i.y, ar1);
        ai1 = fmaf(xr, w_i.y, ai1); ai1 = fmaf( xi, w_r.y, ai1);
        ar2 = fmaf(xr, w_r.z, ar2); ar2 = fmaf(-xi, w_i.z, ar2);
        ai2 = fmaf(xr, w_i.z, ai2); ai2 = fmaf( xi, w_r.z, ai2);
        ar3 = fmaf(xr, w_r.w, ar3); ar3 = fmaf(-xi, w_i.w, ar3);
        ai3 = fmaf(xr, w_i.w, ai3); ai3 = fmaf( xi, w_r.w, ai3);
    }
    const float sc = (m == 0 ? 1.0f : 2.0f) * (1.0f / (float)LL);
    const int par = m & 1, j = m >> 1;
    const int bh = b * HH + h;
    const float vr[4] = {ar0 * sc, ar1 * sc, ar2 * sc, ar3 * sc};
    const float vi[4] = {ai0 * sc, ai1 * sc, ai2 * sc, ai3 * sc};
    #pragma unroll
    for (int t = 0; t < 4; ++t) {
        const size_t idx = (((size_t)bh * 2 + par) * 64 + (o0 + t)) * 64 + 2 * j;
        const __nv_bfloat16 hr = __float2bfloat16(vr[t]);
        g_Ybh[idx] = hr;
        g_Ybl[idx] = __float2bfloat16(vr[t] - __bfloat162float(hr));
        const __nv_bfloat16 hv = __float2bfloat16(vi[t]);
        g_Ybh[idx + 1] = hv;
        g_Ybl[idx + 1] = __float2bfloat16(vi[t] - __bfloat162float(hv));
    }
}

// ---------------------------------------------------------------------------
// Inverse DFT via mma.sync, grid (bh=64, ltile=8, ohalf=2):
//   E[128 l, 32 o] = Ae · Be^T, O likewise; y = E±O. Warp owns 16 l x 32 o.
// ---------------------------------------------------------------------------
__global__ void __launch_bounds__(256) k_invT(float* __restrict__ y) {
    extern __shared__ __align__(16) char smem[];
    const uint32_t sbase = smem_to_u32(smem);
    const int tid = threadIdx.x, wid = tid >> 5, lane = tid & 31;
    const int bh = blockIdx.x, b = bh >> 3, h = bh & 7;
    const int l0 = blockIdx.y * 128;
    const int oh = blockIdx.z;

    // A tiles: 128 l x 64 k, hi/lo, both parities
    for (int idx = tid; idx < 1024; idx += 256) {
        const int row = idx >> 3, ch = idx & 7;
        const uint32_t d = row * ROWB + ch * 16;
        *(uint4*)(smem + OFF_AEH + d) = *((const uint4*)&g_Ah[0][(l0 + row) * 64] + ch);
        *(uint4*)(smem + OFF_AEL + d) = *((const uint4*)&g_Al[0][(l0 + row) * 64] + ch);
        *(uint4*)(smem + OFF_AOH + d) = *((const uint4*)&g_Ah[1][(l0 + row) * 64] + ch);
        *(uint4*)(smem + OFF_AOL + d) = *((const uint4*)&g_Al[1][(l0 + row) * 64] + ch);
    }
    // B tiles: 32 o-rows (this half) x 64 k
    for (int idx = tid; idx < 256; idx += 256) {
        const int row = idx >> 3, ch = idx & 7;
        const uint32_t d = row * ROWB + ch * 16;
        const size_t sE = ((size_t)bh * 2 + 0) * 4096 + (size_t)(oh * 32 + row) * 64;
        const size_t sO = ((size_t)bh * 2 + 1) * 4096 + (size_t)(oh * 32 + row) * 64;
        *(uint4*)(smem + OFF_BEH + d) = *((const uint4*)&g_Ybh[sE] + ch);
        *(uint4*)(smem + OFF_BEL + d) = *((const uint4*)&g_Ybl[sE] + ch);
        *(uint4*)(smem + OFF_BOH + d) = *((const uint4*)&g_Ybh[sO] + ch);
        *(uint4*)(smem + OFF_BOL + d) = *((const uint4*)&g_Ybl[sO] + ch);
    }
    __syncthreads();

    const int m0 = wid * 16;
    float E[4][4], O[4][4];
    #pragma unroll
    for (int n = 0; n < 4; ++n)
        #pragma unroll
        for (int k = 0; k < 4; ++k) { E[n][k] = 0.f; O[n][k] = 0.f; }

    #pragma unroll
    for (int par = 0; par < 2; ++par) {
        float (*acc)[4] = par ? O : E;
        const uint32_t offAH = par ? OFF_AOH : OFF_AEH;
        const uint32_t offAL = par ? OFF_AOL : OFF_AEL;
        const uint32_t offBH = par ? OFF_BOH : OFF_BEH;
        const uint32_t offBL = par ? OFF_BOL : OFF_BEL;
        #pragma unroll
        for (int t = 0; t < 3; ++t) {
            const uint32_t offA = (t == 2) ? offAL : offAH;
            const uint32_t offB = (t == 1) ? offBL : offBH;
            #pragma unroll
            for (int s = 0; s < 4; ++s) {
                const int k0 = s * 16;
                uint32_t a0, a1, a2, a3;
                const uint32_t aaddr = sbase + offA + (m0 + (lane & 15)) * ROWB
                                     + (k0 + (lane >> 4) * 8) * 2;
                ldsm_x4(a0, a1, a2, a3, aaddr);
                const int ll = lane & 15;
                #pragma unroll
                for (int n = 0; n < 4; ++n) {
                    uint32_t b0, b1;
                    const uint32_t baddr = sbase + offB + (n * 8 + (ll & 7)) * ROWB
                                         + (k0 + (ll >> 3) * 8) * 2;
                    ldsm_x2(b0, b1, baddr);
                    mma_bf16(acc[n], a0, a1, a2, a3, b0, b1);
                }
            }
        }
    }

    const int qr = lane >> 2, qc = (lane & 3) * 2;
    float* ybase = y + (size_t)b * LL * (HH * EE) + (size_t)h * EE;
    #pragma unroll
    for (int n = 0; n < 4; ++n) {
        const int o = oh * 32 + n * 8 + qc;
        #pragma unroll
        for (int hr = 0; hr < 2; ++hr) {
            const int l = l0 + m0 + qr + hr * 8;
            const float e0 = E[n][2 * hr], e1 = E[n][2 * hr + 1];
            const float q0 = O[n][2 * hr], q1 = O[n][2 * hr + 1];
            *(float2*)&ybase[(size_t)l * (HH * EE) + o] = make_float2(e0 + q0, e1 + q1);
            *(float2*)&ybase[(size_t)(l + LHALF) * (HH * EE) + o] = make_float2(e0 - q0, e1 - q1);
        }
    }
}

extern "C" void kernel_launch(void* const* d_in, const int* in_sizes, int n_in,
                              void* d_out, int out_size) {
    (void)in_sizes; (void)n_in; (void)out_size;
    const float* x   = (const float*)d_in[0];
    const float* wre = (const float*)d_in[1];
    const float* wim = (const float*)d_in[2];
    float* y = (float*)d_out;

    cudaFuncSetAttribute(k_fwdT, cudaFuncAttributeMaxDynamicSharedMemorySize, SMEM_FWD);
    cudaFuncSetAttribute(k_invT, cudaFuncAttributeMaxDynamicSharedMemorySize, SMEM_INV);

    k_trans<<<640, 256>>>(wre, wim);
    k_fwdT<<<dim3(64, NKC), 256, SMEM_FWD>>>(x);
    k_mix<<<dim3(MM, HH), 128>>>();
    k_invT<<<dim3(64, 8, 2), 256, SMEM_INV>>>(y);
}